// round 1
// baseline (speedup 1.0000x reference)
#include <cuda_runtime.h>
#include <math.h>

// Problem constants
#define BATCH 16
#define NPATCH 4096
#define KTOK 32
#define DIM 512
#define DHEAD 256
#define SCALE_V 0.0625f   // 256^-0.5

// GEMM tiling
#define BM 32
#define BN 64
#define BKK 32
#define TM 4
#define TN 4
#define NTHREADS 128

#define SPLITK_G 8

// Scratch (no allocation allowed -> device globals)
__device__ float g_Q [BATCH*KTOK*DHEAD];            // 512x256
__device__ float g_Qk[BATCH*KTOK*DIM];              // 512x512
__device__ float g_Gp[SPLITK_G*BATCH*KTOK*DIM];     // split-K partials, 8MB
__device__ float g_G [BATCH*KTOK*DIM];              // 512x512
__device__ float g_F [BATCH*KTOK*DHEAD];            // 512x256

// C[M,N] = alpha * A[M,Kin] @ op(B)  (+ log(clip(bias)) when SCORES)
// TRANS_B: B is [N,Kin] row-major (dot over contiguous Kin)  -> C = A @ B^T
// else:    B is [Kin,N] row-major                            -> C = A @ B
// Batched over blockIdx.z: b = bz % nBatch, split = bz / nBatch.
template<bool TRANS_B, bool SCORES>
__global__ __launch_bounds__(NTHREADS)
void gemm32(const float* __restrict__ A, const float* __restrict__ B,
            float* __restrict__ C, int M, int N, int Kin, int splitK,
            long sA, long sB, long sC,
            float alpha, const float* __restrict__ bias, long sBias, int nBatch)
{
    const int bz = blockIdx.z;
    const int b  = bz % nBatch;
    const int sp = bz / nBatch;
    A += (long)b  * sA;
    B += (long)b  * sB;
    C += (long)bz * sC;
    if (SCORES) bias += (long)b * sBias;

    __shared__ float As[BM][BKK+1];
    __shared__ __align__(16) float Bs[BN*(BKK+1)];

    const int m0 = blockIdx.y * BM;
    const int n0 = blockIdx.x * BN;
    const int tid = threadIdx.x;
    const int tyr = tid >> 4;   // 0..7   (row group, 4 rows each)
    const int txr = tid & 15;   // 0..15  (col group, 4 cols each)

    float acc[TM][TN];
    #pragma unroll
    for (int i = 0; i < TM; i++)
        #pragma unroll
        for (int j = 0; j < TN; j++) acc[i][j] = 0.f;

    const int klen = Kin / splitK;
    const int kbeg = sp * klen;
    const int kend = kbeg + klen;

    for (int k0 = kbeg; k0 < kend; k0 += BKK) {
        // --- load A tile (BM x BKK), coalesced over k ---
        #pragma unroll
        for (int p = 0; p < (BM*BKK)/NTHREADS; ++p) {
            int idx = tid + p*NTHREADS;
            int i = idx >> 5, j = idx & 31;
            As[i][j] = A[(long)(m0+i)*Kin + (k0+j)];
        }
        // --- load B tile ---
        if (TRANS_B) {
            #pragma unroll
            for (int p = 0; p < (BN*BKK)/NTHREADS; ++p) {
                int idx = tid + p*NTHREADS;
                int kk = idx & 31, n = idx >> 5;
                Bs[n*(BKK+1) + kk] = B[(long)(n0+n)*Kin + (k0+kk)];
            }
        } else {
            #pragma unroll
            for (int p = 0; p < (BN*BKK)/NTHREADS; ++p) {
                int idx = tid + p*NTHREADS;
                int n = idx & 63, kk = idx >> 6;
                Bs[kk*BN + n] = B[(long)(k0+kk)*N + (n0+n)];
            }
        }
        __syncthreads();

        #pragma unroll
        for (int kk = 0; kk < BKK; ++kk) {
            float a[TM], bb[TN];
            #pragma unroll
            for (int i = 0; i < TM; i++) a[i] = As[tyr*TM + i][kk];
            if (TRANS_B) {
                #pragma unroll
                for (int j = 0; j < TN; j++) bb[j] = Bs[(txr*TN + j)*(BKK+1) + kk];
            } else {
                float4 bv = *reinterpret_cast<const float4*>(&Bs[kk*BN + txr*TN]);
                bb[0] = bv.x; bb[1] = bv.y; bb[2] = bv.z; bb[3] = bv.w;
            }
            #pragma unroll
            for (int i = 0; i < TM; i++)
                #pragma unroll
                for (int j = 0; j < TN; j++)
                    acc[i][j] = fmaf(a[i], bb[j], acc[i][j]);
        }
        __syncthreads();
    }

    #pragma unroll
    for (int i = 0; i < TM; i++) {
        int m = m0 + tyr*TM + i;
        #pragma unroll
        for (int j = 0; j < TN; j++) {
            int n = n0 + txr*TN + j;
            float v = acc[i][j] * alpha;
            if (SCORES) {
                float pb = fminf(fmaxf(bias[n], 0.1f), 0.9f);
                v += logf(pb);
            }
            C[(long)m*N + n] = v;
        }
    }
}

// Deterministic split-K reduce: G[i] = sum_sp Gp[sp*n + i]
__global__ void reduce_splits(const float* __restrict__ Pp, float* __restrict__ G,
                              int n, int splits)
{
    int i = blockIdx.x*blockDim.x + threadIdx.x;
    if (i < n) {
        float s = 0.f;
        for (int sp = 0; sp < splits; ++sp) s += Pp[(long)sp*n + i];
        G[i] = s;
    }
}

// Row softmax over 4096 cols, in place. One block (256 thr) per row.
__global__ void softmax_rows(float* __restrict__ A)
{
    const int row = blockIdx.x;
    float* p = A + (long)row * NPATCH;
    const int t = threadIdx.x;
    float v[16];
    float mx = -1e30f;
    #pragma unroll
    for (int i = 0; i < 16; i++) { v[i] = p[t + i*256]; mx = fmaxf(mx, v[i]); }
    __shared__ float red[256];
    red[t] = mx; __syncthreads();
    #pragma unroll
    for (int s = 128; s > 0; s >>= 1) {
        if (t < s) red[t] = fmaxf(red[t], red[t+s]);
        __syncthreads();
    }
    mx = red[0]; __syncthreads();
    float sm = 0.f;
    #pragma unroll
    for (int i = 0; i < 16; i++) { v[i] = expf(v[i] - mx); sm += v[i]; }
    red[t] = sm; __syncthreads();
    #pragma unroll
    for (int s = 128; s > 0; s >>= 1) {
        if (t < s) red[t] += red[t+s];
        __syncthreads();
    }
    float inv = 1.f / red[0];
    #pragma unroll
    for (int i = 0; i < 16; i++) p[t + i*256] = v[i] * inv;
}

// L2-normalize rows of 512 cols, in place. One block (128 thr) per row.
__global__ void normalize_rows(float* __restrict__ C)
{
    const int row = blockIdx.x;
    float* p = C + (long)row * DIM;
    const int t = threadIdx.x;
    float v[4]; float ss = 0.f;
    #pragma unroll
    for (int i = 0; i < 4; i++) { v[i] = p[t + i*128]; ss += v[i]*v[i]; }
    __shared__ float red[128];
    red[t] = ss; __syncthreads();
    #pragma unroll
    for (int s = 64; s > 0; s >>= 1) {
        if (t < s) red[t] += red[t+s];
        __syncthreads();
    }
    float inv = 1.f / (sqrtf(red[0]) + 1e-8f);
    #pragma unroll
    for (int i = 0; i < 4; i++) p[t + i*128] = v[i] * inv;
}

extern "C" void kernel_launch(void* const* d_in, const int* in_sizes, int n_in,
                              void* d_out, int out_size)
{
    const float* E  = (const float*)d_in[0];  // [16,4096,512]
    const float* T  = (const float*)d_in[1];  // [16,32,512]
    const float* P  = (const float*)d_in[2];  // [16,4096]
    const float* Wq = (const float*)d_in[3];  // [256,512]
    const float* Wk = (const float*)d_in[4];  // [256,512]
    const float* Wv = (const float*)d_in[5];  // [256,512]
    const float* Wo = (const float*)d_in[6];  // [512,256]

    float* outF = (float*)d_out;                               // [16,32,512]
    float* outA = (float*)d_out + (long)BATCH*KTOK*DIM;        // [16,32,4096]

    float *pQ, *pQk, *pGp, *pG, *pF;
    cudaGetSymbolAddress((void**)&pQ,  g_Q);
    cudaGetSymbolAddress((void**)&pQk, g_Qk);
    cudaGetSymbolAddress((void**)&pGp, g_Gp);
    cudaGetSymbolAddress((void**)&pG,  g_G);
    cudaGetSymbolAddress((void**)&pF,  g_F);

    dim3 blk(NTHREADS);

    // 1) Q = T @ Wq^T : [512,256], Kin=512 (NT)
    gemm32<true,false><<<dim3(DHEAD/BN, (BATCH*KTOK)/BM, 1), blk>>>(
        T, Wq, pQ, BATCH*KTOK, DHEAD, DIM, 1, 0, 0, 0, 1.f, nullptr, 0, 1);

    // 2) Qk = Q @ Wk : [512,512], Kin=256 (NN; Wk is [d=256, m=512])
    gemm32<false,false><<<dim3(DIM/BN, (BATCH*KTOK)/BM, 1), blk>>>(
        pQ, Wk, pQk, BATCH*KTOK, DIM, DHEAD, 1, 0, 0, 0, 1.f, nullptr, 0, 1);

    // 3) scores[b,k,n] = SCALE * Qk_b @ E_b^T + log(clip(P_b))  -> into A region
    gemm32<true,true><<<dim3(NPATCH/BN, 1, BATCH), blk>>>(
        pQk, E, outA, KTOK, NPATCH, DIM, 1,
        (long)KTOK*DIM, (long)NPATCH*DIM, (long)KTOK*NPATCH,
        SCALE_V, P, NPATCH, BATCH);

    // 4) softmax rows (512 rows of 4096), in place
    softmax_rows<<<BATCH*KTOK, 256>>>(outA);

    // 5) G_b = A_b @ E_b : [32,512], Kin=4096 (NN), split-K=8 for occupancy
    gemm32<false,false><<<dim3(DIM/BN, 1, BATCH*SPLITK_G), blk>>>(
        outA, E, pGp, KTOK, DIM, NPATCH, SPLITK_G,
        (long)KTOK*NPATCH, (long)NPATCH*DIM, (long)KTOK*DIM,
        1.f, nullptr, 0, BATCH);

    {
        int n = BATCH*KTOK*DIM;
        reduce_splits<<<(n + 255)/256, 256>>>(pGp, pG, n, SPLITK_G);
    }

    // 6) F = G @ Wv^T : [512,256], Kin=512 (NT)
    gemm32<true,false><<<dim3(DHEAD/BN, (BATCH*KTOK)/BM, 1), blk>>>(
        pG, Wv, pF, BATCH*KTOK, DHEAD, DIM, 1, 0, 0, 0, 1.f, nullptr, 0, 1);

    // 7) out = F @ Wo^T : [512,512], Kin=256 (NT; Wo is [m=512, d=256])
    gemm32<true,false><<<dim3(DIM/BN, (BATCH*KTOK)/BM, 1), blk>>>(
        pF, Wo, outF, BATCH*KTOK, DIM, DHEAD, 1, 0, 0, 0, 1.f, nullptr, 0, 1);

    // 8) L2-normalize rows of outF (512 rows of 512), in place
    normalize_rows<<<BATCH*KTOK, 128>>>(outF);
}

// round 2
// speedup vs baseline: 1.4424x; 1.4424x over previous
#include <cuda_runtime.h>
#include <cuda_bf16.h>
#include <math.h>
#include <stdint.h>

// Problem constants
#define BATCH 16
#define NPATCH 4096
#define KTOK 32
#define DIM 512
#define DHEAD 256
#define SCALE_V 0.0625f   // 256^-0.5

#define SPLITK_G 8

// Scratch (no allocation allowed -> device globals)
__device__ float g_Q [BATCH*KTOK*DHEAD];            // 512x256
__device__ float g_Qk[BATCH*KTOK*DIM];              // 512x512
__device__ float g_Gp[SPLITK_G*BATCH*KTOK*DIM];     // split-K partials
__device__ float g_G [BATCH*KTOK*DIM];              // 512x512
__device__ float g_F [BATCH*KTOK*DHEAD];            // 512x256

// ---------------------------------------------------------------------------
// Tensor-core GEMM, fp32-in/fp32-out via bf16 hi/lo split (3 MMAs: hh+hl+lh).
// C[M,N] = alpha * A[M,Kin] @ op(B)   (+ log(clip(bias,0.1,0.9)) if SCORES)
//   TRANS_B=false: B gmem is [N,Kin] row-major  (dot over contiguous Kin)
//   TRANS_B=true : B gmem is [Kin,N] row-major
// Tiles: BM=32, BN=128, BK=32. 256 threads = 8 warps (2 m-warps x 4 n-warps).
// Batched over blockIdx.z: b = bz % nBatch, splitK slice = bz / nBatch.
// ---------------------------------------------------------------------------

#define LDSM4(R0,R1,R2,R3,ADDR) \
    asm volatile("ldmatrix.sync.aligned.m8n8.x4.shared.b16 {%0,%1,%2,%3}, [%4];" \
        : "=r"(R0),"=r"(R1),"=r"(R2),"=r"(R3) : "r"(ADDR))

#define LDSM4T(R0,R1,R2,R3,ADDR) \
    asm volatile("ldmatrix.sync.aligned.m8n8.x4.trans.shared.b16 {%0,%1,%2,%3}, [%4];" \
        : "=r"(R0),"=r"(R1),"=r"(R2),"=r"(R3) : "r"(ADDR))

#define MMA16816(C,A,B0,B1) \
    asm volatile("mma.sync.aligned.m16n8k16.row.col.f32.bf16.bf16.f32 " \
        "{%0,%1,%2,%3},{%4,%5,%6,%7},{%8,%9},{%0,%1,%2,%3};" \
        : "+f"((C)[0]),"+f"((C)[1]),"+f"((C)[2]),"+f"((C)[3]) \
        : "r"((A)[0]),"r"((A)[1]),"r"((A)[2]),"r"((A)[3]),"r"(B0),"r"(B1))

__device__ __forceinline__ uint32_t cvta_s(const void* p) {
    return (uint32_t)__cvta_generic_to_shared(p);
}

// Split a float4 into hi/lo bf16 pairs packed as uint2 (4 bf16 = 8 bytes each).
__device__ __forceinline__ void cvt_split4(float4 v, uint2 &hi, uint2 &lo) {
    __nv_bfloat162 h0 = __floats2bfloat162_rn(v.x, v.y);
    __nv_bfloat162 h1 = __floats2bfloat162_rn(v.z, v.w);
    float rx = v.x - __bfloat162float(h0.x);
    float ry = v.y - __bfloat162float(h0.y);
    float rz = v.z - __bfloat162float(h1.x);
    float rw = v.w - __bfloat162float(h1.y);
    __nv_bfloat162 l0 = __floats2bfloat162_rn(rx, ry);
    __nv_bfloat162 l1 = __floats2bfloat162_rn(rz, rw);
    hi.x = *(uint32_t*)&h0; hi.y = *(uint32_t*)&h1;
    lo.x = *(uint32_t*)&l0; lo.y = *(uint32_t*)&l1;
}

// smem byte-offset layout
#define SA_H   0          // A hi tile: 32 rows x pitch 80B  = 2560
#define SA_L   2560
#define SB_H   5120       // B tile: max(128*80, 32*272) = 10240
#define SB_L   15360
#define SMEM_BYTES 25600
#define PITCH_A   80      // 40 bf16 elems
#define PITCH_B   80      // non-trans: [n][k], 40 elems
#define PITCH_BT  272     // trans: [k][n], 136 elems

template<bool TRANS_B, bool SCORES>
__global__ __launch_bounds__(256)
void gemm_tc(const float* __restrict__ A, const float* __restrict__ B,
             float* __restrict__ C, int N, int Kin, int splitK,
             long sA, long sB, long sC, float alpha,
             const float* __restrict__ bias, long sBias, int nBatch)
{
    __shared__ __align__(16) unsigned char sm[SMEM_BYTES];

    const int bz = blockIdx.z;
    const int b  = bz % nBatch;
    const int sp = bz / nBatch;
    A += (long)b  * sA;
    B += (long)b  * sB;
    C += (long)bz * sC;
    const float* biasb = SCORES ? (bias + (long)b * sBias) : nullptr;

    const int m0 = blockIdx.y * 32;
    const int n0 = blockIdx.x * 128;
    const int tid  = threadIdx.x;
    const int lane = tid & 31;
    const int warp = tid >> 5;
    const int mw = warp >> 2;     // 0..1
    const int nw = warp & 3;      // 0..3

    float acc[4][4];
    #pragma unroll
    for (int j = 0; j < 4; j++)
        #pragma unroll
        for (int r = 0; r < 4; r++) acc[j][r] = 0.f;

    const int klen = Kin / splitK;
    const int kbeg = sp * klen;
    const int kend = kbeg + klen;

    // ldmatrix base addresses (per warp/lane, constant over k loop)
    const uint32_t aRow  = mw*16 + (lane & 15);
    const uint32_t aColB = (lane >> 4) * 16;                 // bytes
    const uint32_t aAddrH = cvta_s(sm + SA_H) + aRow*PITCH_A + aColB;
    const uint32_t aAddrL = aAddrH + (SA_L - SA_H);

    uint32_t bAddrH[2], bAddrL[2];
    if (!TRANS_B) {
        #pragma unroll
        for (int jj = 0; jj < 2; jj++) {
            uint32_t nrow = nw*32 + jj*16 + (lane & 7) + ((lane >> 4) & 1)*8;
            uint32_t kB   = ((lane >> 3) & 1) * 16;          // bytes
            bAddrH[jj] = cvta_s(sm + SB_H) + nrow*PITCH_B + kB;
            bAddrL[jj] = bAddrH[jj] + (SB_L - SB_H);
        }
    } else {
        #pragma unroll
        for (int jj = 0; jj < 2; jj++) {
            uint32_t krow = (lane & 15);
            uint32_t nB   = (nw*32 + jj*16)*2 + ((lane >> 4) & 1)*16;  // bytes
            bAddrH[jj] = cvta_s(sm + SB_H) + krow*PITCH_BT + nB;
            bAddrL[jj] = bAddrH[jj] + (SB_L - SB_H);
        }
    }

    for (int k0 = kbeg; k0 < kend; k0 += 32) {
        // --- stage A tile [32 m x 32 k] (1 float4 per thread) ---
        {
            int m  = tid >> 3;
            int k4 = tid & 7;
            float4 v = *(const float4*)(A + (long)(m0+m)*Kin + k0 + 4*k4);
            uint2 hi, lo; cvt_split4(v, hi, lo);
            *(uint2*)(sm + SA_H + m*PITCH_A + 8*k4) = hi;
            *(uint2*)(sm + SA_L + m*PITCH_A + 8*k4) = lo;
        }
        // --- stage B tile ---
        if (!TRANS_B) {
            #pragma unroll
            for (int p = 0; p < 4; ++p) {
                int lin = tid + p*256;
                int n  = lin >> 3;
                int k4 = lin & 7;
                float4 v = *(const float4*)(B + (long)(n0+n)*Kin + k0 + 4*k4);
                uint2 hi, lo; cvt_split4(v, hi, lo);
                *(uint2*)(sm + SB_H + n*PITCH_B + 8*k4) = hi;
                *(uint2*)(sm + SB_L + n*PITCH_B + 8*k4) = lo;
            }
        } else {
            #pragma unroll
            for (int p = 0; p < 4; ++p) {
                int lin = tid + p*256;
                int k  = lin >> 5;
                int n4 = lin & 31;
                float4 v = *(const float4*)(B + (long)(k0+k)*N + n0 + 4*n4);
                uint2 hi, lo; cvt_split4(v, hi, lo);
                *(uint2*)(sm + SB_H + k*PITCH_BT + 8*n4) = hi;
                *(uint2*)(sm + SB_L + k*PITCH_BT + 8*n4) = lo;
            }
        }
        __syncthreads();

        #pragma unroll
        for (int kt = 0; kt < 2; ++kt) {
            uint32_t ah[4], al[4];
            LDSM4(ah[0],ah[1],ah[2],ah[3], aAddrH + kt*32);
            LDSM4(al[0],al[1],al[2],al[3], aAddrL + kt*32);

            uint32_t bh[4][2], bl[4][2];
            #pragma unroll
            for (int jj = 0; jj < 2; ++jj) {
                uint32_t r0,r1,r2,r3;
                if (!TRANS_B) {
                    LDSM4(r0,r1,r2,r3, bAddrH[jj] + kt*32);
                    bh[2*jj][0]=r0; bh[2*jj][1]=r1; bh[2*jj+1][0]=r2; bh[2*jj+1][1]=r3;
                    LDSM4(r0,r1,r2,r3, bAddrL[jj] + kt*32);
                    bl[2*jj][0]=r0; bl[2*jj][1]=r1; bl[2*jj+1][0]=r2; bl[2*jj+1][1]=r3;
                } else {
                    LDSM4T(r0,r1,r2,r3, bAddrH[jj] + kt*16*PITCH_BT);
                    bh[2*jj][0]=r0; bh[2*jj][1]=r1; bh[2*jj+1][0]=r2; bh[2*jj+1][1]=r3;
                    LDSM4T(r0,r1,r2,r3, bAddrL[jj] + kt*16*PITCH_BT);
                    bl[2*jj][0]=r0; bl[2*jj][1]=r1; bl[2*jj+1][0]=r2; bl[2*jj+1][1]=r3;
                }
            }
            #pragma unroll
            for (int j = 0; j < 4; ++j) {
                MMA16816(acc[j], ah, bh[j][0], bh[j][1]);
                MMA16816(acc[j], ah, bl[j][0], bl[j][1]);
                MMA16816(acc[j], al, bh[j][0], bh[j][1]);
            }
        }
        __syncthreads();
    }

    // --- epilogue ---
    const int mrow = m0 + mw*16 + (lane >> 2);
    #pragma unroll
    for (int j = 0; j < 4; ++j) {
        int n = n0 + nw*32 + j*8 + 2*(lane & 3);
        float v0 = acc[j][0]*alpha, v1 = acc[j][1]*alpha;
        float v2 = acc[j][2]*alpha, v3 = acc[j][3]*alpha;
        if (SCORES) {
            float p0 = logf(fminf(fmaxf(biasb[n],   0.1f), 0.9f));
            float p1 = logf(fminf(fmaxf(biasb[n+1], 0.1f), 0.9f));
            v0 += p0; v1 += p1; v2 += p0; v3 += p1;
        }
        C[(long)mrow*N + n]       = v0;
        C[(long)mrow*N + n + 1]   = v1;
        C[(long)(mrow+8)*N + n]   = v2;
        C[(long)(mrow+8)*N + n+1] = v3;
    }
}

// Deterministic split-K reduce: G[i] = sum_sp Gp[sp*n + i]
__global__ void reduce_splits(const float* __restrict__ Pp, float* __restrict__ G,
                              int n, int splits)
{
    int i = blockIdx.x*blockDim.x + threadIdx.x;
    if (i < n) {
        float s = 0.f;
        for (int sp = 0; sp < splits; ++sp) s += Pp[(long)sp*n + i];
        G[i] = s;
    }
}

// Row softmax over 4096 cols, in place. One block (256 thr) per row.
__global__ void softmax_rows(float* __restrict__ A)
{
    const int row = blockIdx.x;
    float* p = A + (long)row * NPATCH;
    const int t = threadIdx.x;
    float v[16];
    float mx = -1e30f;
    #pragma unroll
    for (int i = 0; i < 16; i++) { v[i] = p[t + i*256]; mx = fmaxf(mx, v[i]); }
    __shared__ float red[256];
    red[t] = mx; __syncthreads();
    #pragma unroll
    for (int s = 128; s > 0; s >>= 1) {
        if (t < s) red[t] = fmaxf(red[t], red[t+s]);
        __syncthreads();
    }
    mx = red[0]; __syncthreads();
    float sm = 0.f;
    #pragma unroll
    for (int i = 0; i < 16; i++) { v[i] = expf(v[i] - mx); sm += v[i]; }
    red[t] = sm; __syncthreads();
    #pragma unroll
    for (int s = 128; s > 0; s >>= 1) {
        if (t < s) red[t] += red[t+s];
        __syncthreads();
    }
    float inv = 1.f / red[0];
    #pragma unroll
    for (int i = 0; i < 16; i++) p[t + i*256] = v[i] * inv;
}

// L2-normalize rows of 512 cols, in place. One block (128 thr) per row.
__global__ void normalize_rows(float* __restrict__ C)
{
    const int row = blockIdx.x;
    float* p = C + (long)row * DIM;
    const int t = threadIdx.x;
    float v[4]; float ss = 0.f;
    #pragma unroll
    for (int i = 0; i < 4; i++) { v[i] = p[t + i*128]; ss += v[i]*v[i]; }
    __shared__ float red[128];
    red[t] = ss; __syncthreads();
    #pragma unroll
    for (int s = 64; s > 0; s >>= 1) {
        if (t < s) red[t] += red[t+s];
        __syncthreads();
    }
    float inv = 1.f / (sqrtf(red[0]) + 1e-8f);
    #pragma unroll
    for (int i = 0; i < 4; i++) p[t + i*128] = v[i] * inv;
}

extern "C" void kernel_launch(void* const* d_in, const int* in_sizes, int n_in,
                              void* d_out, int out_size)
{
    const float* E  = (const float*)d_in[0];  // [16,4096,512]
    const float* T  = (const float*)d_in[1];  // [16,32,512]
    const float* P  = (const float*)d_in[2];  // [16,4096]
    const float* Wq = (const float*)d_in[3];  // [256,512]
    const float* Wk = (const float*)d_in[4];  // [256,512]
    const float* Wv = (const float*)d_in[5];  // [256,512]
    const float* Wo = (const float*)d_in[6];  // [512,256]

    float* outF = (float*)d_out;                               // [16,32,512]
    float* outA = (float*)d_out + (long)BATCH*KTOK*DIM;        // [16,32,4096]

    float *pQ, *pQk, *pGp, *pG, *pF;
    cudaGetSymbolAddress((void**)&pQ,  g_Q);
    cudaGetSymbolAddress((void**)&pQk, g_Qk);
    cudaGetSymbolAddress((void**)&pGp, g_Gp);
    cudaGetSymbolAddress((void**)&pG,  g_G);
    cudaGetSymbolAddress((void**)&pF,  g_F);

    dim3 blk(256);

    // 1) Q = T @ Wq^T : M=512, N=256, Kin=512 (B=[N,K] non-trans)
    gemm_tc<false,false><<<dim3(DHEAD/128, (BATCH*KTOK)/32, 1), blk>>>(
        T, Wq, pQ, DHEAD, DIM, 1, 0, 0, 0, 1.f, nullptr, 0, 1);

    // 2) Qk = Q @ Wk : M=512, N=512, Kin=256 (B=[K,N] trans)
    gemm_tc<true,false><<<dim3(DIM/128, (BATCH*KTOK)/32, 1), blk>>>(
        pQ, Wk, pQk, DIM, DHEAD, 1, 0, 0, 0, 1.f, nullptr, 0, 1);

    // 3) scores[b] = SCALE * Qk_b @ E_b^T + log(clip(P_b))  (batched, B=[N,K])
    gemm_tc<false,true><<<dim3(NPATCH/128, 1, BATCH), blk>>>(
        pQk, E, outA, NPATCH, DIM, 1,
        (long)KTOK*DIM, (long)NPATCH*DIM, (long)KTOK*NPATCH,
        SCALE_V, P, NPATCH, BATCH);

    // 4) softmax rows (512 rows of 4096), in place
    softmax_rows<<<BATCH*KTOK, 256>>>(outA);

    // 5) G_b = A_b @ E_b : M=32, N=512, Kin=4096 (B=[K,N] trans), split-K=8
    gemm_tc<true,false><<<dim3(DIM/128, 1, BATCH*SPLITK_G), blk>>>(
        outA, E, pGp, DIM, NPATCH, SPLITK_G,
        (long)KTOK*NPATCH, (long)NPATCH*DIM, (long)KTOK*DIM,
        1.f, nullptr, 0, BATCH);

    {
        int n = BATCH*KTOK*DIM;
        reduce_splits<<<(n + 255)/256, 256>>>(pGp, pG, n, SPLITK_G);
    }

    // 6) F = G @ Wv^T : M=512, N=256, Kin=512 (non-trans)
    gemm_tc<false,false><<<dim3(DHEAD/128, (BATCH*KTOK)/32, 1), blk>>>(
        pG, Wv, pF, DHEAD, DIM, 1, 0, 0, 0, 1.f, nullptr, 0, 1);

    // 7) out = F @ Wo^T : M=512, N=512, Kin=256 (non-trans; Wo is [N=512,K=256])
    gemm_tc<false,false><<<dim3(DIM/128, (BATCH*KTOK)/32, 1), blk>>>(
        pF, Wo, outF, DIM, DHEAD, 1, 0, 0, 0, 1.f, nullptr, 0, 1);

    // 8) L2-normalize rows of outF (512 rows of 512), in place
    normalize_rows<<<BATCH*KTOK, 128>>>(outF);
}

// round 3
// speedup vs baseline: 1.7430x; 1.2084x over previous
#include <cuda_runtime.h>
#include <cuda_bf16.h>
#include <cuda_fp16.h>
#include <math.h>
#include <stdint.h>

// Problem constants
#define BATCH 16
#define NPATCH 4096
#define KTOK 32
#define DIM 512
#define DHEAD 256
#define SCALE_V 0.0625f   // 256^-0.5

#define SPLITK_G 8
#define NCHUNK 32         // NPATCH/128 score chunks

// Scratch (no allocation allowed -> device globals)
__device__ float g_Q   [BATCH*KTOK*DHEAD];
__device__ float g_Qk  [BATCH*KTOK*DIM];
__device__ float g_Gp  [SPLITK_G*BATCH*KTOK*DIM];
__device__ float g_G   [BATCH*KTOK*DIM];
__device__ float g_F   [BATCH*KTOK*DHEAD];
__device__ float g_rows[BATCH*KTOK*NCHUNK];
__device__ float g_inv [BATCH*KTOK];

// ---------------------------------------------------------------------------

#define LDSM4(R0,R1,R2,R3,ADDR) \
    asm volatile("ldmatrix.sync.aligned.m8n8.x4.shared.b16 {%0,%1,%2,%3}, [%4];" \
        : "=r"(R0),"=r"(R1),"=r"(R2),"=r"(R3) : "r"(ADDR))

#define LDSM4T(R0,R1,R2,R3,ADDR) \
    asm volatile("ldmatrix.sync.aligned.m8n8.x4.trans.shared.b16 {%0,%1,%2,%3}, [%4];" \
        : "=r"(R0),"=r"(R1),"=r"(R2),"=r"(R3) : "r"(ADDR))

#define MMA_BF16(C,A,B0,B1) \
    asm volatile("mma.sync.aligned.m16n8k16.row.col.f32.bf16.bf16.f32 " \
        "{%0,%1,%2,%3},{%4,%5,%6,%7},{%8,%9},{%0,%1,%2,%3};" \
        : "+f"((C)[0]),"+f"((C)[1]),"+f"((C)[2]),"+f"((C)[3]) \
        : "r"((A)[0]),"r"((A)[1]),"r"((A)[2]),"r"((A)[3]),"r"(B0),"r"(B1))

#define MMA_F16(C,A,B0,B1) \
    asm volatile("mma.sync.aligned.m16n8k16.row.col.f32.f16.f16.f32 " \
        "{%0,%1,%2,%3},{%4,%5,%6,%7},{%8,%9},{%0,%1,%2,%3};" \
        : "+f"((C)[0]),"+f"((C)[1]),"+f"((C)[2]),"+f"((C)[3]) \
        : "r"((A)[0]),"r"((A)[1]),"r"((A)[2]),"r"((A)[3]),"r"(B0),"r"(B1))

__device__ __forceinline__ uint32_t cvta_s(const void* p) {
    return (uint32_t)__cvta_generic_to_shared(p);
}

__device__ __forceinline__ uint2 cvt_h4(float4 v) {
    __half2 h0 = __floats2half2_rn(v.x, v.y);
    __half2 h1 = __floats2half2_rn(v.z, v.w);
    uint2 r; r.x = *(uint32_t*)&h0; r.y = *(uint32_t*)&h1; return r;
}

__device__ __forceinline__ void cvt_split4(float4 v, uint2 &hi, uint2 &lo) {
    __nv_bfloat162 h0 = __floats2bfloat162_rn(v.x, v.y);
    __nv_bfloat162 h1 = __floats2bfloat162_rn(v.z, v.w);
    float rx = v.x - __bfloat162float(h0.x);
    float ry = v.y - __bfloat162float(h0.y);
    float rz = v.z - __bfloat162float(h1.x);
    float rw = v.w - __bfloat162float(h1.y);
    __nv_bfloat162 l0 = __floats2bfloat162_rn(rx, ry);
    __nv_bfloat162 l1 = __floats2bfloat162_rn(rz, rw);
    hi.x = *(uint32_t*)&h0; hi.y = *(uint32_t*)&h1;
    lo.x = *(uint32_t*)&l0; lo.y = *(uint32_t*)&l1;
}

#define PITCH_A   80
#define PITCH_B   80
#define PITCH_BT  272

// ===========================================================================
// fp16 single-MMA tensor-core GEMM, register-prefetch pipelined.
// BM=32, BN=128, BK=32, 256 threads (2 m-warps x 4 n-warps).
// C = alpha * A @ op(B); EXPS: C = exp(alpha*acc + log(clip(bias,0.1,0.9)))
// and per-block unnormalized-softmax row sums go to rowsOut.
// ===========================================================================
#define HS_A 0
#define HS_B 2560
#define HS_BYTES (2560 + 10240)

template<bool TRANS_B, bool EXPS>
__global__ __launch_bounds__(256)
void gemm_h(const float* __restrict__ A, const float* __restrict__ B,
            float* __restrict__ C, int N, int Kin, int splitK,
            long sA, long sB, long sC, float alpha,
            const float* __restrict__ bias, long sBias, int nBatch,
            float* __restrict__ rowsOut)
{
    __shared__ __align__(16) unsigned char sm[HS_BYTES];

    const int bz = blockIdx.z;
    const int b  = bz % nBatch;
    const int sp = bz / nBatch;
    A += (long)b  * sA;
    B += (long)b  * sB;
    C += (long)bz * sC;
    const float* biasb = EXPS ? (bias + (long)b * sBias) : nullptr;

    const int m0 = blockIdx.y * 32;
    const int n0 = blockIdx.x * 128;
    const int tid  = threadIdx.x;
    const int lane = tid & 31;
    const int warp = tid >> 5;
    const int mw = warp >> 2;
    const int nw = warp & 3;

    float acc[4][4];
    #pragma unroll
    for (int j = 0; j < 4; j++)
        #pragma unroll
        for (int r = 0; r < 4; r++) acc[j][r] = 0.f;

    const int klen = Kin / splitK;
    const int kbeg = sp * klen;
    const int kend = kbeg + klen;

    const uint32_t aAddr = cvta_s(sm + HS_A)
        + (mw*16 + (lane & 15))*PITCH_A + (lane >> 4)*16;
    uint32_t bAddr[2];
    if (!TRANS_B) {
        #pragma unroll
        for (int jj = 0; jj < 2; jj++) {
            uint32_t nrow = nw*32 + jj*16 + (lane & 7) + ((lane >> 4) & 1)*8;
            bAddr[jj] = cvta_s(sm + HS_B) + nrow*PITCH_B + ((lane >> 3) & 1)*16;
        }
    } else {
        #pragma unroll
        for (int jj = 0; jj < 2; jj++) {
            uint32_t nB = (nw*32 + jj*16)*2 + ((lane >> 4) & 1)*16;
            bAddr[jj] = cvta_s(sm + HS_B) + (lane & 15)*PITCH_BT + nB;
        }
    }

    const int am  = tid >> 3, ak4 = tid & 7;
    const float* aG = A + (long)(m0 + am)*Kin + 4*ak4;

    float4 pa, pb[4];
    pa = *(const float4*)(aG + kbeg);
    if (!TRANS_B) {
        #pragma unroll
        for (int p = 0; p < 4; ++p) {
            int lin = tid + p*256;
            pb[p] = *(const float4*)(B + (long)(n0 + (lin >> 3))*Kin + kbeg + 4*(lin & 7));
        }
    } else {
        #pragma unroll
        for (int p = 0; p < 4; ++p) {
            int lin = tid + p*256;
            pb[p] = *(const float4*)(B + (long)(kbeg + (lin >> 5))*N + n0 + 4*(lin & 31));
        }
    }

    for (int k0 = kbeg; k0 < kend; k0 += 32) {
        *(uint2*)(sm + HS_A + am*PITCH_A + 8*ak4) = cvt_h4(pa);
        if (!TRANS_B) {
            #pragma unroll
            for (int p = 0; p < 4; ++p) {
                int lin = tid + p*256;
                *(uint2*)(sm + HS_B + (lin >> 3)*PITCH_B + 8*(lin & 7)) = cvt_h4(pb[p]);
            }
        } else {
            #pragma unroll
            for (int p = 0; p < 4; ++p) {
                int lin = tid + p*256;
                *(uint2*)(sm + HS_B + (lin >> 5)*PITCH_BT + 8*(lin & 31)) = cvt_h4(pb[p]);
            }
        }
        __syncthreads();

        int kn = k0 + 32;
        if (kn < kend) {
            pa = *(const float4*)(aG + kn);
            if (!TRANS_B) {
                #pragma unroll
                for (int p = 0; p < 4; ++p) {
                    int lin = tid + p*256;
                    pb[p] = *(const float4*)(B + (long)(n0 + (lin >> 3))*Kin + kn + 4*(lin & 7));
                }
            } else {
                #pragma unroll
                for (int p = 0; p < 4; ++p) {
                    int lin = tid + p*256;
                    pb[p] = *(const float4*)(B + (long)(kn + (lin >> 5))*N + n0 + 4*(lin & 31));
                }
            }
        }

        #pragma unroll
        for (int kt = 0; kt < 2; ++kt) {
            uint32_t a[4];
            LDSM4(a[0],a[1],a[2],a[3], aAddr + kt*32);
            uint32_t bf[4][2];
            #pragma unroll
            for (int jj = 0; jj < 2; ++jj) {
                uint32_t r0,r1,r2,r3;
                if (!TRANS_B) {
                    LDSM4(r0,r1,r2,r3, bAddr[jj] + kt*32);
                } else {
                    LDSM4T(r0,r1,r2,r3, bAddr[jj] + kt*16*PITCH_BT);
                }
                bf[2*jj][0]=r0; bf[2*jj][1]=r1; bf[2*jj+1][0]=r2; bf[2*jj+1][1]=r3;
            }
            #pragma unroll
            for (int j = 0; j < 4; ++j)
                MMA_F16(acc[j], a, bf[j][0], bf[j][1]);
        }
        __syncthreads();
    }

    const int mrow = m0 + mw*16 + (lane >> 2);
    float rsum0 = 0.f, rsum8 = 0.f;
    #pragma unroll
    for (int j = 0; j < 4; ++j) {
        int n = n0 + nw*32 + j*8 + 2*(lane & 3);
        float v0 = acc[j][0]*alpha, v1 = acc[j][1]*alpha;
        float v2 = acc[j][2]*alpha, v3 = acc[j][3]*alpha;
        if (EXPS) {
            float p0 = __logf(fminf(fmaxf(biasb[n],   0.1f), 0.9f));
            float p1 = __logf(fminf(fmaxf(biasb[n+1], 0.1f), 0.9f));
            v0 = __expf(v0 + p0); v1 = __expf(v1 + p1);
            v2 = __expf(v2 + p0); v3 = __expf(v3 + p1);
            rsum0 += v0 + v1; rsum8 += v2 + v3;
        }
        C[(long)mrow*N + n]       = v0;
        C[(long)mrow*N + n + 1]   = v1;
        C[(long)(mrow+8)*N + n]   = v2;
        C[(long)(mrow+8)*N + n+1] = v3;
    }

    if (EXPS) {
        rsum0 += __shfl_xor_sync(0xffffffffu, rsum0, 1);
        rsum0 += __shfl_xor_sync(0xffffffffu, rsum0, 2);
        rsum8 += __shfl_xor_sync(0xffffffffu, rsum8, 1);
        rsum8 += __shfl_xor_sync(0xffffffffu, rsum8, 2);
        float (*srow)[4] = (float(*)[4])sm;
        if ((lane & 3) == 0) {
            srow[mw*16 + (lane >> 2)][nw]     = rsum0;
            srow[mw*16 + 8 + (lane >> 2)][nw] = rsum8;
        }
        __syncthreads();
        if (tid < 32) {
            float s = srow[tid][0] + srow[tid][1] + srow[tid][2] + srow[tid][3];
            rowsOut[((long)b*KTOK + tid)*gridDim.x + blockIdx.x] = s;
        }
    }
}

// ===========================================================================
// bf16 hi/lo split GEMM (3 MMAs) — F-side chain, near-fp32 accuracy.
// ===========================================================================
#define SA_H   0
#define SA_L   2560
#define SB_H   5120
#define SB_L   15360
#define SMEM_BYTES 25600

__global__ __launch_bounds__(256)
void gemm_tc_nt(const float* __restrict__ A, const float* __restrict__ B,
                float* __restrict__ C, int N, int Kin)
{
    __shared__ __align__(16) unsigned char sm[SMEM_BYTES];

    const int m0 = blockIdx.y * 32;
    const int n0 = blockIdx.x * 128;
    const int tid  = threadIdx.x;
    const int lane = tid & 31;
    const int warp = tid >> 5;
    const int mw = warp >> 2;
    const int nw = warp & 3;

    float acc[4][4];
    #pragma unroll
    for (int j = 0; j < 4; j++)
        #pragma unroll
        for (int r = 0; r < 4; r++) acc[j][r] = 0.f;

    const uint32_t aAddrH = cvta_s(sm + SA_H)
        + (mw*16 + (lane & 15))*PITCH_A + (lane >> 4)*16;
    const uint32_t aAddrL = aAddrH + (SA_L - SA_H);

    uint32_t bAddrH[2], bAddrL[2];
    #pragma unroll
    for (int jj = 0; jj < 2; jj++) {
        uint32_t nrow = nw*32 + jj*16 + (lane & 7) + ((lane >> 4) & 1)*8;
        bAddrH[jj] = cvta_s(sm + SB_H) + nrow*PITCH_B + ((lane >> 3) & 1)*16;
        bAddrL[jj] = bAddrH[jj] + (SB_L - SB_H);
    }

    for (int k0 = 0; k0 < Kin; k0 += 32) {
        {
            int m  = tid >> 3, k4 = tid & 7;
            float4 v = *(const float4*)(A + (long)(m0+m)*Kin + k0 + 4*k4);
            uint2 hi, lo; cvt_split4(v, hi, lo);
            *(uint2*)(sm + SA_H + m*PITCH_A + 8*k4) = hi;
            *(uint2*)(sm + SA_L + m*PITCH_A + 8*k4) = lo;
        }
        #pragma unroll
        for (int p = 0; p < 4; ++p) {
            int lin = tid + p*256;
            int n = lin >> 3, k4 = lin & 7;
            float4 v = *(const float4*)(B + (long)(n0+n)*Kin + k0 + 4*k4);
            uint2 hi, lo; cvt_split4(v, hi, lo);
            *(uint2*)(sm + SB_H + n*PITCH_B + 8*k4) = hi;
            *(uint2*)(sm + SB_L + n*PITCH_B + 8*k4) = lo;
        }
        __syncthreads();

        #pragma unroll
        for (int kt = 0; kt < 2; ++kt) {
            uint32_t ah[4], al[4];
            LDSM4(ah[0],ah[1],ah[2],ah[3], aAddrH + kt*32);
            LDSM4(al[0],al[1],al[2],al[3], aAddrL + kt*32);
            uint32_t bh[4][2], bl[4][2];
            #pragma unroll
            for (int jj = 0; jj < 2; ++jj) {
                uint32_t r0,r1,r2,r3;
                LDSM4(r0,r1,r2,r3, bAddrH[jj] + kt*32);
                bh[2*jj][0]=r0; bh[2*jj][1]=r1; bh[2*jj+1][0]=r2; bh[2*jj+1][1]=r3;
                LDSM4(r0,r1,r2,r3, bAddrL[jj] + kt*32);
                bl[2*jj][0]=r0; bl[2*jj][1]=r1; bl[2*jj+1][0]=r2; bl[2*jj+1][1]=r3;
            }
            #pragma unroll
            for (int j = 0; j < 4; ++j) {
                MMA_BF16(acc[j], ah, bh[j][0], bh[j][1]);
                MMA_BF16(acc[j], ah, bl[j][0], bl[j][1]);
                MMA_BF16(acc[j], al, bh[j][0], bh[j][1]);
            }
        }
        __syncthreads();
    }

    const int mrow = m0 + mw*16 + (lane >> 2);
    #pragma unroll
    for (int j = 0; j < 4; ++j) {
        int n = n0 + nw*32 + j*8 + 2*(lane & 3);
        C[(long)mrow*N + n]       = acc[j][0];
        C[(long)mrow*N + n + 1]   = acc[j][1];
        C[(long)(mrow+8)*N + n]   = acc[j][2];
        C[(long)(mrow+8)*N + n+1] = acc[j][3];
    }
}

// ---------------------------------------------------------------------------
__global__ void reduce_splits(const float* __restrict__ Pp, float* __restrict__ G,
                              int n, int splits)
{
    int i = blockIdx.x*blockDim.x + threadIdx.x;
    if (i < n) {
        float s = 0.f;
        for (int sp = 0; sp < splits; ++sp) s += Pp[(long)sp*n + i];
        G[i] = s;
    }
}

__global__ void rowinv(const float* __restrict__ rows, float* __restrict__ inv)
{
    int r = blockIdx.x*blockDim.x + threadIdx.x;
    if (r < BATCH*KTOK) {
        float s = 0.f;
        #pragma unroll
        for (int c = 0; c < NCHUNK; ++c) s += rows[r*NCHUNK + c];
        inv[r] = 1.f / s;
    }
}

__global__ void scaleA(float4* __restrict__ A4, const float* __restrict__ inv)
{
    int i = blockIdx.x*blockDim.x + threadIdx.x;   // 524288 total
    float s = inv[i >> 10];                        // 1024 float4 per row
    float4 v = A4[i];
    v.x *= s; v.y *= s; v.z *= s; v.w *= s;
    A4[i] = v;
}

__global__ void normalize_rows(float* __restrict__ C)
{
    const int row = blockIdx.x;
    float* p = C + (long)row * DIM;
    const int t = threadIdx.x;
    float v[4]; float ss = 0.f;
    #pragma unroll
    for (int i = 0; i < 4; i++) { v[i] = p[t + i*128]; ss += v[i]*v[i]; }
    __shared__ float red[128];
    red[t] = ss; __syncthreads();
    #pragma unroll
    for (int s = 64; s > 0; s >>= 1) {
        if (t < s) red[t] += red[t+s];
        __syncthreads();
    }
    float inv = 1.f / (sqrtf(red[0]) + 1e-8f);
    #pragma unroll
    for (int i = 0; i < 4; i++) p[t + i*128] = v[i] * inv;
}

extern "C" void kernel_launch(void* const* d_in, const int* in_sizes, int n_in,
                              void* d_out, int out_size)
{
    const float* E  = (const float*)d_in[0];
    const float* T  = (const float*)d_in[1];
    const float* P  = (const float*)d_in[2];
    const float* Wq = (const float*)d_in[3];
    const float* Wk = (const float*)d_in[4];
    const float* Wv = (const float*)d_in[5];
    const float* Wo = (const float*)d_in[6];

    float* outF = (float*)d_out;
    float* outA = (float*)d_out + (long)BATCH*KTOK*DIM;

    float *pQ, *pQk, *pGp, *pG, *pF, *pRows, *pInv;
    cudaGetSymbolAddress((void**)&pQ,    g_Q);
    cudaGetSymbolAddress((void**)&pQk,   g_Qk);
    cudaGetSymbolAddress((void**)&pGp,   g_Gp);
    cudaGetSymbolAddress((void**)&pG,    g_G);
    cudaGetSymbolAddress((void**)&pF,    g_F);
    cudaGetSymbolAddress((void**)&pRows, g_rows);
    cudaGetSymbolAddress((void**)&pInv,  g_inv);

    dim3 blk(256);

    // 1) Q = T @ Wq^T  (fp16 single)
    gemm_h<false,false><<<dim3(DHEAD/128, 16, 1), blk>>>(
        T, Wq, pQ, DHEAD, DIM, 1, 0, 0, 0, 1.f, nullptr, 0, 1, nullptr);

    // 2) Qk = Q @ Wk  (fp16 single, trans)
    gemm_h<true,false><<<dim3(DIM/128, 16, 1), blk>>>(
        pQ, Wk, pQk, DIM, DHEAD, 1, 0, 0, 0, 1.f, nullptr, 0, 1, nullptr);

    // 3) expS = exp(SCALE*Qk@E^T + log(clip(P))) with per-block rowsums
    gemm_h<false,true><<<dim3(NCHUNK, 1, BATCH), blk>>>(
        pQk, E, outA, NPATCH, DIM, 1,
        (long)KTOK*DIM, (long)NPATCH*DIM, (long)KTOK*NPATCH,
        SCALE_V, P, NPATCH, BATCH, pRows);

    // 4) inverse row sums
    rowinv<<<2, 256>>>(pRows, pInv);

    // 5) G = expS @ E (unnormalized; L2-normalize absorbs it), split-K=8
    gemm_h<true,false><<<dim3(DIM/128, 1, BATCH*SPLITK_G), blk>>>(
        outA, E, pGp, DIM, NPATCH, SPLITK_G,
        (long)KTOK*NPATCH, (long)NPATCH*DIM, (long)KTOK*DIM,
        1.f, nullptr, 0, BATCH, nullptr);

    {
        int n = BATCH*KTOK*DIM;
        reduce_splits<<<(n + 255)/256, 256>>>(pGp, pG, n, SPLITK_G);
    }

    // 6) F = G @ Wv^T  (bf16 hi/lo)
    gemm_tc_nt<<<dim3(DHEAD/128, 16, 1), blk>>>(pG, Wv, pF, DHEAD, DIM);

    // 7) out = F @ Wo^T  (bf16 hi/lo)
    gemm_tc_nt<<<dim3(DIM/128, 16, 1), blk>>>(pF, Wo, outF, DIM, DHEAD);

    // 8) L2-normalize outF rows
    normalize_rows<<<BATCH*KTOK, 128>>>(outF);

    // 9) A output normalization
    scaleA<<<2048, 256>>>((float4*)outA, pInv);
}

// round 4
// speedup vs baseline: 2.2448x; 1.2879x over previous
#include <cuda_runtime.h>
#include <cuda_bf16.h>
#include <cuda_fp16.h>
#include <math.h>
#include <stdint.h>

// Problem constants
#define BATCH 16
#define NPATCH 4096
#define KTOK 32
#define DIM 512
#define DHEAD 256
#define SCALE_V 0.0625f   // 256^-0.5

#define SPLITS 8          // n-splits for fused kernel (grid = 8 x 16 = 128 blocks)

// Scratch (no allocation allowed -> device globals)
__device__ float g_Q   [BATCH*KTOK*DHEAD];
__device__ float g_Qk  [BATCH*KTOK*DIM];
__device__ float g_Gp  [SPLITS*BATCH*KTOK*DIM];
__device__ float g_G   [BATCH*KTOK*DIM];
__device__ float g_F   [BATCH*KTOK*DHEAD];
__device__ float g_rows[BATCH*KTOK*SPLITS];

// ---------------------------------------------------------------------------

#define LDSM4(R0,R1,R2,R3,ADDR) \
    asm volatile("ldmatrix.sync.aligned.m8n8.x4.shared.b16 {%0,%1,%2,%3}, [%4];" \
        : "=r"(R0),"=r"(R1),"=r"(R2),"=r"(R3) : "r"(ADDR))

#define LDSM4T(R0,R1,R2,R3,ADDR) \
    asm volatile("ldmatrix.sync.aligned.m8n8.x4.trans.shared.b16 {%0,%1,%2,%3}, [%4];" \
        : "=r"(R0),"=r"(R1),"=r"(R2),"=r"(R3) : "r"(ADDR))

#define MMA_BF16(C,A,B0,B1) \
    asm volatile("mma.sync.aligned.m16n8k16.row.col.f32.bf16.bf16.f32 " \
        "{%0,%1,%2,%3},{%4,%5,%6,%7},{%8,%9},{%0,%1,%2,%3};" \
        : "+f"((C)[0]),"+f"((C)[1]),"+f"((C)[2]),"+f"((C)[3]) \
        : "r"((A)[0]),"r"((A)[1]),"r"((A)[2]),"r"((A)[3]),"r"(B0),"r"(B1))

#define MMA_F16(C,A,B0,B1) \
    asm volatile("mma.sync.aligned.m16n8k16.row.col.f32.f16.f16.f32 " \
        "{%0,%1,%2,%3},{%4,%5,%6,%7},{%8,%9},{%0,%1,%2,%3};" \
        : "+f"((C)[0]),"+f"((C)[1]),"+f"((C)[2]),"+f"((C)[3]) \
        : "r"((A)[0]),"r"((A)[1]),"r"((A)[2]),"r"((A)[3]),"r"(B0),"r"(B1))

__device__ __forceinline__ uint32_t cvta_s(const void* p) {
    return (uint32_t)__cvta_generic_to_shared(p);
}

__device__ __forceinline__ uint2 cvt_h4(float4 v) {
    __half2 h0 = __floats2half2_rn(v.x, v.y);
    __half2 h1 = __floats2half2_rn(v.z, v.w);
    uint2 r; r.x = *(uint32_t*)&h0; r.y = *(uint32_t*)&h1; return r;
}

__device__ __forceinline__ void cvt_split4(float4 v, uint2 &hi, uint2 &lo) {
    __nv_bfloat162 h0 = __floats2bfloat162_rn(v.x, v.y);
    __nv_bfloat162 h1 = __floats2bfloat162_rn(v.z, v.w);
    float rx = v.x - __bfloat162float(h0.x);
    float ry = v.y - __bfloat162float(h0.y);
    float rz = v.z - __bfloat162float(h1.x);
    float rw = v.w - __bfloat162float(h1.y);
    __nv_bfloat162 l0 = __floats2bfloat162_rn(rx, ry);
    __nv_bfloat162 l1 = __floats2bfloat162_rn(rz, rw);
    hi.x = *(uint32_t*)&h0; hi.y = *(uint32_t*)&h1;
    lo.x = *(uint32_t*)&l0; lo.y = *(uint32_t*)&l1;
}

// ===========================================================================
// FUSED attention kernel: per (split, batch) block.
//   Loop over 4 n-chunks of 128:
//     phase1: S[32,128] = Qk[32,512] @ Echunk^T   (E staged fp16, pipelined)
//     epilogue: expS = exp(S*scale + logP); write A out; rowsum accumulate
//     phase2: Gacc[32,512] += expS[32,128] @ Echunk (reuses smem E tile)
//   End: write G partial + row sums.
// 256 threads = 8 warps (2 m-warps x 4 n-warps).
// ===========================================================================
#define QK_OFF   0
#define QK_PITCH 1040          // 512 fp16 + 8 pad (pitch%128B==16B -> conflict-free)
#define E_OFF    33280         // 32*1040
#define E_PITCH  1040
#define ES_OFF   166400        // E_OFF + 128*1040
#define ES_PITCH 272           // 128 fp16 + 8 pad
#define RED_OFF  175104        // ES_OFF + 32*272
#define SMEM_FUSED 175616      // RED_OFF + 512

__global__ __launch_bounds__(256, 1)
void fused_attn(const float* __restrict__ Qk, const float* __restrict__ E,
                const float* __restrict__ P, float* __restrict__ outA,
                float* __restrict__ Gp, float* __restrict__ rows)
{
    extern __shared__ __align__(16) unsigned char sm[];
    const int sp = blockIdx.x;         // 0..7
    const int b  = blockIdx.y;         // 0..15
    const int tid  = threadIdx.x;
    const int lane = tid & 31;
    const int warp = tid >> 5;
    const int mw = warp >> 2;          // 0..1
    const int nw = warp & 3;           // 0..3

    const float* Eb  = E  + (long)b*NPATCH*DIM;
    const float* Qkb = Qk + (long)b*KTOK*DIM;
    const float* Pb  = P  + (long)b*NPATCH;
    float*       Ab  = outA + (long)b*KTOK*NPATCH;

    // ---- load Qk [32,512] fp32 -> fp16 smem (resident) ----
    #pragma unroll
    for (int p = 0; p < 16; ++p) {
        int lin = tid + p*256;
        int r = lin >> 7, c4 = lin & 127;
        float4 v = *(const float4*)(Qkb + r*DIM + 4*c4);
        *(uint2*)(sm + QK_OFF + r*QK_PITCH + 8*c4) = cvt_h4(v);
    }

    float accG[4][4][4];
    #pragma unroll
    for (int d = 0; d < 4; ++d)
        #pragma unroll
        for (int j = 0; j < 4; ++j)
            #pragma unroll
            for (int r = 0; r < 4; ++r) accG[d][j][r] = 0.f;
    float rsum0 = 0.f, rsum8 = 0.f;

    const uint32_t smb = cvta_s(sm);
    // phase1 A (Qk, non-trans): m16 rows, k contiguous
    const uint32_t aQkBase = smb + QK_OFF + (mw*16 + (lane & 15))*QK_PITCH + (lane >> 4)*16;
    // phase1 B (E tile, non-trans): n rows, k contiguous
    uint32_t b1Base[2];
    #pragma unroll
    for (int jj = 0; jj < 2; ++jj)
        b1Base[jj] = smb + E_OFF
            + (nw*32 + jj*16 + (lane & 7) + ((lane >> 4) & 1)*8)*E_PITCH
            + ((lane >> 3) & 1)*16;
    // phase2 A (expS, non-trans)
    const uint32_t aEsBase = smb + ES_OFF + (mw*16 + (lane & 15))*ES_PITCH + (lane >> 4)*16;
    // phase2 B (E tile, trans): k(n) rows, N(d) contiguous
    uint32_t b2Base[2];
    #pragma unroll
    for (int jj = 0; jj < 2; ++jj)
        b2Base[jj] = smb + E_OFF + (lane & 15)*E_PITCH
            + (nw*32 + jj*16)*2 + ((lane >> 4) & 1)*16;

    // per-thread E sub-block mapping: 128 rows x 32 d; 4 float4 per thread
    const int er  = tid >> 3;          // base row stride handled per p
    const int ec4 = tid & 7;

    const int nbase = sp * (NPATCH/SPLITS);   // 512-wide slice

    float4 pfA[4], pfB[4];
    // prefetch chunk 0, subs 0 and 1
    #pragma unroll
    for (int p = 0; p < 4; ++p)
        pfA[p] = *(const float4*)(Eb + (long)(nbase + er + p*32)*DIM + 0*32 + 4*ec4);
    #pragma unroll
    for (int p = 0; p < 4; ++p)
        pfB[p] = *(const float4*)(Eb + (long)(nbase + er + p*32)*DIM + 1*32 + 4*ec4);

    for (int c = 0; c < 4; ++c) {
        const int n0 = nbase + c*128;
        float acc[4][4];
        #pragma unroll
        for (int j = 0; j < 4; ++j)
            #pragma unroll
            for (int r = 0; r < 4; ++r) acc[j][r] = 0.f;

        // ---- phase 1: pipelined E staging + S MMA ----
        #pragma unroll
        for (int i = 0; i < 16; i += 2) {
            // store sub i (pfA)
            #pragma unroll
            for (int p = 0; p < 4; ++p)
                *(uint2*)(sm + E_OFF + (er + p*32)*E_PITCH + i*64 + 8*ec4) = cvt_h4(pfA[p]);
            __syncthreads();
            if (i + 2 < 16) {
                #pragma unroll
                for (int p = 0; p < 4; ++p)
                    pfA[p] = *(const float4*)(Eb + (long)(n0 + er + p*32)*DIM + (i+2)*32 + 4*ec4);
            }
            // compute sub i
            #pragma unroll
            for (int kt = 0; kt < 2; ++kt) {
                uint32_t a[4];
                LDSM4(a[0],a[1],a[2],a[3], aQkBase + i*64 + kt*32);
                uint32_t bf[4][2];
                #pragma unroll
                for (int jj = 0; jj < 2; ++jj) {
                    uint32_t r0,r1,r2,r3;
                    LDSM4(r0,r1,r2,r3, b1Base[jj] + i*64 + kt*32);
                    bf[2*jj][0]=r0; bf[2*jj][1]=r1; bf[2*jj+1][0]=r2; bf[2*jj+1][1]=r3;
                }
                #pragma unroll
                for (int j = 0; j < 4; ++j)
                    MMA_F16(acc[j], a, bf[j][0], bf[j][1]);
            }
            // store sub i+1 (pfB)
            #pragma unroll
            for (int p = 0; p < 4; ++p)
                *(uint2*)(sm + E_OFF + (er + p*32)*E_PITCH + (i+1)*64 + 8*ec4) = cvt_h4(pfB[p]);
            __syncthreads();
            if (i + 3 < 16) {
                #pragma unroll
                for (int p = 0; p < 4; ++p)
                    pfB[p] = *(const float4*)(Eb + (long)(n0 + er + p*32)*DIM + (i+3)*32 + 4*ec4);
            }
            // compute sub i+1
            #pragma unroll
            for (int kt = 0; kt < 2; ++kt) {
                uint32_t a[4];
                LDSM4(a[0],a[1],a[2],a[3], aQkBase + (i+1)*64 + kt*32);
                uint32_t bf[4][2];
                #pragma unroll
                for (int jj = 0; jj < 2; ++jj) {
                    uint32_t r0,r1,r2,r3;
                    LDSM4(r0,r1,r2,r3, b1Base[jj] + (i+1)*64 + kt*32);
                    bf[2*jj][0]=r0; bf[2*jj][1]=r1; bf[2*jj+1][0]=r2; bf[2*jj+1][1]=r3;
                }
                #pragma unroll
                for (int j = 0; j < 4; ++j)
                    MMA_F16(acc[j], a, bf[j][0], bf[j][1]);
            }
        }

        // ---- epilogue: exp + A out + expS smem + row sums ----
        {
            const int mrow = mw*16 + (lane >> 2);
            #pragma unroll
            for (int j = 0; j < 4; ++j) {
                int nl = nw*32 + j*8 + 2*(lane & 3);
                int gn = n0 + nl;
                float lp0 = __logf(fminf(fmaxf(Pb[gn],   0.1f), 0.9f));
                float lp1 = __logf(fminf(fmaxf(Pb[gn+1], 0.1f), 0.9f));
                float v0 = __expf(acc[j][0]*SCALE_V + lp0);
                float v1 = __expf(acc[j][1]*SCALE_V + lp1);
                float v2 = __expf(acc[j][2]*SCALE_V + lp0);
                float v3 = __expf(acc[j][3]*SCALE_V + lp1);
                rsum0 += v0 + v1; rsum8 += v2 + v3;
                float2 f01 = make_float2(v0, v1);
                float2 f23 = make_float2(v2, v3);
                *(float2*)(Ab + (long)mrow*NPATCH + gn)     = f01;
                *(float2*)(Ab + (long)(mrow+8)*NPATCH + gn) = f23;
                __half2 h01 = __floats2half2_rn(v0, v1);
                __half2 h23 = __floats2half2_rn(v2, v3);
                *(uint32_t*)(sm + ES_OFF + mrow*ES_PITCH + nl*2)     = *(uint32_t*)&h01;
                *(uint32_t*)(sm + ES_OFF + (mrow+8)*ES_PITCH + nl*2) = *(uint32_t*)&h23;
            }
        }
        __syncthreads();

        // prefetch next chunk's first two sub-blocks (overlaps phase 2)
        if (c + 1 < 4) {
            int nn = nbase + (c+1)*128;
            #pragma unroll
            for (int p = 0; p < 4; ++p)
                pfA[p] = *(const float4*)(Eb + (long)(nn + er + p*32)*DIM + 0*32 + 4*ec4);
            #pragma unroll
            for (int p = 0; p < 4; ++p)
                pfB[p] = *(const float4*)(Eb + (long)(nn + er + p*32)*DIM + 1*32 + 4*ec4);
        }

        // ---- phase 2: G += expS @ Echunk ----
        #pragma unroll
        for (int ks = 0; ks < 8; ++ks) {
            uint32_t a[4];
            LDSM4(a[0],a[1],a[2],a[3], aEsBase + ks*32);
            #pragma unroll
            for (int ds = 0; ds < 4; ++ds) {
                uint32_t bf[4][2];
                #pragma unroll
                for (int jj = 0; jj < 2; ++jj) {
                    uint32_t r0,r1,r2,r3;
                    LDSM4T(r0,r1,r2,r3, b2Base[jj] + ks*16*E_PITCH + ds*256);
                    bf[2*jj][0]=r0; bf[2*jj][1]=r1; bf[2*jj+1][0]=r2; bf[2*jj+1][1]=r3;
                }
                #pragma unroll
                for (int j = 0; j < 4; ++j)
                    MMA_F16(accG[ds][j], a, bf[j][0], bf[j][1]);
            }
        }
        __syncthreads();   // E tile + expS reusable next chunk
    }

    // ---- write G partial ----
    {
        float* Gpb = Gp + ((long)(sp*BATCH + b)*KTOK)*DIM;
        const int mrow = mw*16 + (lane >> 2);
        #pragma unroll
        for (int ds = 0; ds < 4; ++ds) {
            #pragma unroll
            for (int j = 0; j < 4; ++j) {
                int d = ds*128 + nw*32 + j*8 + 2*(lane & 3);
                float2 f01 = make_float2(accG[ds][j][0], accG[ds][j][1]);
                float2 f23 = make_float2(accG[ds][j][2], accG[ds][j][3]);
                *(float2*)(Gpb + (long)mrow*DIM + d)     = f01;
                *(float2*)(Gpb + (long)(mrow+8)*DIM + d) = f23;
            }
        }
    }

    // ---- row-sum partials ----
    rsum0 += __shfl_xor_sync(0xffffffffu, rsum0, 1);
    rsum0 += __shfl_xor_sync(0xffffffffu, rsum0, 2);
    rsum8 += __shfl_xor_sync(0xffffffffu, rsum8, 1);
    rsum8 += __shfl_xor_sync(0xffffffffu, rsum8, 2);
    float (*srow)[4] = (float(*)[4])(sm + RED_OFF);
    if ((lane & 3) == 0) {
        srow[mw*16 + (lane >> 2)][nw]     = rsum0;
        srow[mw*16 + 8 + (lane >> 2)][nw] = rsum8;
    }
    __syncthreads();
    if (tid < 32) {
        float s = srow[tid][0] + srow[tid][1] + srow[tid][2] + srow[tid][3];
        rows[(b*KTOK + tid)*SPLITS + sp] = s;
    }
}

// ===========================================================================
// fp16 single-MMA GEMM for the small projections (Q, Qk).
// BM=32, BN=128, BK=32, 256 threads. C = A[M,Kin] @ op(B).
// ===========================================================================
#define PITCH_A   80
#define PITCH_B   80
#define PITCH_BT  272
#define HS_A 0
#define HS_B 2560
#define HS_BYTES (2560 + 10240)

template<bool TRANS_B>
__global__ __launch_bounds__(256)
void gemm_h(const float* __restrict__ A, const float* __restrict__ B,
            float* __restrict__ C, int N, int Kin)
{
    __shared__ __align__(16) unsigned char sm[HS_BYTES];

    const int m0 = blockIdx.y * 32;
    const int n0 = blockIdx.x * 128;
    const int tid  = threadIdx.x;
    const int lane = tid & 31;
    const int warp = tid >> 5;
    const int mw = warp >> 2;
    const int nw = warp & 3;

    float acc[4][4];
    #pragma unroll
    for (int j = 0; j < 4; j++)
        #pragma unroll
        for (int r = 0; r < 4; r++) acc[j][r] = 0.f;

    const uint32_t aAddr = cvta_s(sm + HS_A)
        + (mw*16 + (lane & 15))*PITCH_A + (lane >> 4)*16;
    uint32_t bAddr[2];
    if (!TRANS_B) {
        #pragma unroll
        for (int jj = 0; jj < 2; jj++) {
            uint32_t nrow = nw*32 + jj*16 + (lane & 7) + ((lane >> 4) & 1)*8;
            bAddr[jj] = cvta_s(sm + HS_B) + nrow*PITCH_B + ((lane >> 3) & 1)*16;
        }
    } else {
        #pragma unroll
        for (int jj = 0; jj < 2; jj++) {
            uint32_t nB = (nw*32 + jj*16)*2 + ((lane >> 4) & 1)*16;
            bAddr[jj] = cvta_s(sm + HS_B) + (lane & 15)*PITCH_BT + nB;
        }
    }

    const int am  = tid >> 3, ak4 = tid & 7;
    const float* aG = A + (long)(m0 + am)*Kin + 4*ak4;

    float4 pa, pb[4];
    pa = *(const float4*)(aG);
    if (!TRANS_B) {
        #pragma unroll
        for (int p = 0; p < 4; ++p) {
            int lin = tid + p*256;
            pb[p] = *(const float4*)(B + (long)(n0 + (lin >> 3))*Kin + 4*(lin & 7));
        }
    } else {
        #pragma unroll
        for (int p = 0; p < 4; ++p) {
            int lin = tid + p*256;
            pb[p] = *(const float4*)(B + (long)(lin >> 5)*N + n0 + 4*(lin & 31));
        }
    }

    for (int k0 = 0; k0 < Kin; k0 += 32) {
        *(uint2*)(sm + HS_A + am*PITCH_A + 8*ak4) = cvt_h4(pa);
        if (!TRANS_B) {
            #pragma unroll
            for (int p = 0; p < 4; ++p) {
                int lin = tid + p*256;
                *(uint2*)(sm + HS_B + (lin >> 3)*PITCH_B + 8*(lin & 7)) = cvt_h4(pb[p]);
            }
        } else {
            #pragma unroll
            for (int p = 0; p < 4; ++p) {
                int lin = tid + p*256;
                *(uint2*)(sm + HS_B + (lin >> 5)*PITCH_BT + 8*(lin & 31)) = cvt_h4(pb[p]);
            }
        }
        __syncthreads();

        int kn = k0 + 32;
        if (kn < Kin) {
            pa = *(const float4*)(aG + kn);
            if (!TRANS_B) {
                #pragma unroll
                for (int p = 0; p < 4; ++p) {
                    int lin = tid + p*256;
                    pb[p] = *(const float4*)(B + (long)(n0 + (lin >> 3))*Kin + kn + 4*(lin & 7));
                }
            } else {
                #pragma unroll
                for (int p = 0; p < 4; ++p) {
                    int lin = tid + p*256;
                    pb[p] = *(const float4*)(B + (long)(kn + (lin >> 5))*N + n0 + 4*(lin & 31));
                }
            }
        }

        #pragma unroll
        for (int kt = 0; kt < 2; ++kt) {
            uint32_t a[4];
            LDSM4(a[0],a[1],a[2],a[3], aAddr + kt*32);
            uint32_t bf[4][2];
            #pragma unroll
            for (int jj = 0; jj < 2; ++jj) {
                uint32_t r0,r1,r2,r3;
                if (!TRANS_B) {
                    LDSM4(r0,r1,r2,r3, bAddr[jj] + kt*32);
                } else {
                    LDSM4T(r0,r1,r2,r3, bAddr[jj] + kt*16*PITCH_BT);
                }
                bf[2*jj][0]=r0; bf[2*jj][1]=r1; bf[2*jj+1][0]=r2; bf[2*jj+1][1]=r3;
            }
            #pragma unroll
            for (int j = 0; j < 4; ++j)
                MMA_F16(acc[j], a, bf[j][0], bf[j][1]);
        }
        __syncthreads();
    }

    const int mrow = m0 + mw*16 + (lane >> 2);
    #pragma unroll
    for (int j = 0; j < 4; ++j) {
        int n = n0 + nw*32 + j*8 + 2*(lane & 3);
        C[(long)mrow*N + n]       = acc[j][0];
        C[(long)mrow*N + n + 1]   = acc[j][1];
        C[(long)(mrow+8)*N + n]   = acc[j][2];
        C[(long)(mrow+8)*N + n+1] = acc[j][3];
    }
}

// ===========================================================================
// bf16 hi/lo split GEMM (3 MMAs) — F-side chain, near-fp32 accuracy.
// ===========================================================================
#define SA_H   0
#define SA_L   2560
#define SB_H   5120
#define SB_L   15360
#define SMEM_BYTES 25600

__global__ __launch_bounds__(256)
void gemm_tc_nt(const float* __restrict__ A, const float* __restrict__ B,
                float* __restrict__ C, int N, int Kin)
{
    __shared__ __align__(16) unsigned char sm[SMEM_BYTES];

    const int m0 = blockIdx.y * 32;
    const int n0 = blockIdx.x * 128;
    const int tid  = threadIdx.x;
    const int lane = tid & 31;
    const int warp = tid >> 5;
    const int mw = warp >> 2;
    const int nw = warp & 3;

    float acc[4][4];
    #pragma unroll
    for (int j = 0; j < 4; j++)
        #pragma unroll
        for (int r = 0; r < 4; r++) acc[j][r] = 0.f;

    const uint32_t aAddrH = cvta_s(sm + SA_H)
        + (mw*16 + (lane & 15))*PITCH_A + (lane >> 4)*16;
    const uint32_t aAddrL = aAddrH + (SA_L - SA_H);

    uint32_t bAddrH[2], bAddrL[2];
    #pragma unroll
    for (int jj = 0; jj < 2; jj++) {
        uint32_t nrow = nw*32 + jj*16 + (lane & 7) + ((lane >> 4) & 1)*8;
        bAddrH[jj] = cvta_s(sm + SB_H) + nrow*PITCH_B + ((lane >> 3) & 1)*16;
        bAddrL[jj] = bAddrH[jj] + (SB_L - SB_H);
    }

    for (int k0 = 0; k0 < Kin; k0 += 32) {
        {
            int m  = tid >> 3, k4 = tid & 7;
            float4 v = *(const float4*)(A + (long)(m0+m)*Kin + k0 + 4*k4);
            uint2 hi, lo; cvt_split4(v, hi, lo);
            *(uint2*)(sm + SA_H + m*PITCH_A + 8*k4) = hi;
            *(uint2*)(sm + SA_L + m*PITCH_A + 8*k4) = lo;
        }
        #pragma unroll
        for (int p = 0; p < 4; ++p) {
            int lin = tid + p*256;
            int n = lin >> 3, k4 = lin & 7;
            float4 v = *(const float4*)(B + (long)(n0+n)*Kin + k0 + 4*k4);
            uint2 hi, lo; cvt_split4(v, hi, lo);
            *(uint2*)(sm + SB_H + n*PITCH_B + 8*k4) = hi;
            *(uint2*)(sm + SB_L + n*PITCH_B + 8*k4) = lo;
        }
        __syncthreads();

        #pragma unroll
        for (int kt = 0; kt < 2; ++kt) {
            uint32_t ah[4], al[4];
            LDSM4(ah[0],ah[1],ah[2],ah[3], aAddrH + kt*32);
            LDSM4(al[0],al[1],al[2],al[3], aAddrL + kt*32);
            uint32_t bh[4][2], bl[4][2];
            #pragma unroll
            for (int jj = 0; jj < 2; ++jj) {
                uint32_t r0,r1,r2,r3;
                LDSM4(r0,r1,r2,r3, bAddrH[jj] + kt*32);
                bh[2*jj][0]=r0; bh[2*jj][1]=r1; bh[2*jj+1][0]=r2; bh[2*jj+1][1]=r3;
                LDSM4(r0,r1,r2,r3, bAddrL[jj] + kt*32);
                bl[2*jj][0]=r0; bl[2*jj][1]=r1; bl[2*jj+1][0]=r2; bl[2*jj+1][1]=r3;
            }
            #pragma unroll
            for (int j = 0; j < 4; ++j) {
                MMA_BF16(acc[j], ah, bh[j][0], bh[j][1]);
                MMA_BF16(acc[j], ah, bl[j][0], bl[j][1]);
                MMA_BF16(acc[j], al, bh[j][0], bh[j][1]);
            }
        }
        __syncthreads();
    }

    const int mrow = m0 + mw*16 + (lane >> 2);
    #pragma unroll
    for (int j = 0; j < 4; ++j) {
        int n = n0 + nw*32 + j*8 + 2*(lane & 3);
        C[(long)mrow*N + n]       = acc[j][0];
        C[(long)mrow*N + n + 1]   = acc[j][1];
        C[(long)(mrow+8)*N + n]   = acc[j][2];
        C[(long)(mrow+8)*N + n+1] = acc[j][3];
    }
}

// ---------------------------------------------------------------------------
__global__ void reduce_splits(const float* __restrict__ Pp, float* __restrict__ G,
                              int n, int splits)
{
    int i = blockIdx.x*blockDim.x + threadIdx.x;
    if (i < n) {
        float s = 0.f;
        for (int sp = 0; sp < splits; ++sp) s += Pp[(long)sp*n + i];
        G[i] = s;
    }
}

// One block per A-row: reduce 8 split row-sums, then scale 4096 elements.
__global__ void scaleA2(float* __restrict__ A, const float* __restrict__ rows)
{
    __shared__ float sinv;
    const int r = blockIdx.x;
    if (threadIdx.x == 0) {
        float s = 0.f;
        #pragma unroll
        for (int c = 0; c < SPLITS; ++c) s += rows[r*SPLITS + c];
        sinv = 1.f / s;
    }
    __syncthreads();
    float s = sinv;
    float4* p = (float4*)(A + (long)r*NPATCH);
    #pragma unroll
    for (int i = 0; i < 4; ++i) {
        float4 v = p[threadIdx.x + i*256];
        v.x *= s; v.y *= s; v.z *= s; v.w *= s;
        p[threadIdx.x + i*256] = v;
    }
}

__global__ void normalize_rows(float* __restrict__ C)
{
    const int row = blockIdx.x;
    float* p = C + (long)row * DIM;
    const int t = threadIdx.x;
    float v[4]; float ss = 0.f;
    #pragma unroll
    for (int i = 0; i < 4; i++) { v[i] = p[t + i*128]; ss += v[i]*v[i]; }
    __shared__ float red[128];
    red[t] = ss; __syncthreads();
    #pragma unroll
    for (int s = 64; s > 0; s >>= 1) {
        if (t < s) red[t] += red[t+s];
        __syncthreads();
    }
    float inv = 1.f / (sqrtf(red[0]) + 1e-8f);
    #pragma unroll
    for (int i = 0; i < 4; i++) p[t + i*128] = v[i] * inv;
}

extern "C" void kernel_launch(void* const* d_in, const int* in_sizes, int n_in,
                              void* d_out, int out_size)
{
    const float* E  = (const float*)d_in[0];
    const float* T  = (const float*)d_in[1];
    const float* P  = (const float*)d_in[2];
    const float* Wq = (const float*)d_in[3];
    const float* Wk = (const float*)d_in[4];
    const float* Wv = (const float*)d_in[5];
    const float* Wo = (const float*)d_in[6];

    float* outF = (float*)d_out;
    float* outA = (float*)d_out + (long)BATCH*KTOK*DIM;

    float *pQ, *pQk, *pGp, *pG, *pF, *pRows;
    cudaGetSymbolAddress((void**)&pQ,    g_Q);
    cudaGetSymbolAddress((void**)&pQk,   g_Qk);
    cudaGetSymbolAddress((void**)&pGp,   g_Gp);
    cudaGetSymbolAddress((void**)&pG,    g_G);
    cudaGetSymbolAddress((void**)&pF,    g_F);
    cudaGetSymbolAddress((void**)&pRows, g_rows);

    cudaFuncSetAttribute(fused_attn,
        cudaFuncAttributeMaxDynamicSharedMemorySize, SMEM_FUSED);

    dim3 blk(256);

    // 1) Q = T @ Wq^T  (fp16 single)
    gemm_h<false><<<dim3(DHEAD/128, 16, 1), blk>>>(T, Wq, pQ, DHEAD, DIM);

    // 2) Qk = Q @ Wk  (fp16 single, trans)
    gemm_h<true><<<dim3(DIM/128, 16, 1), blk>>>(pQ, Wk, pQk, DIM, DHEAD);

    // 3) FUSED: expS (A out) + row sums + G partials
    fused_attn<<<dim3(SPLITS, BATCH, 1), blk, SMEM_FUSED>>>(
        pQk, E, P, outA, pGp, pRows);

    // 4) reduce G partials
    {
        int n = BATCH*KTOK*DIM;
        reduce_splits<<<(n + 255)/256, 256>>>(pGp, pG, n, SPLITS);
    }

    // 5) F = G @ Wv^T  (bf16 hi/lo)
    gemm_tc_nt<<<dim3(DHEAD/128, 16, 1), blk>>>(pG, Wv, pF, DHEAD, DIM);

    // 6) out = F @ Wo^T  (bf16 hi/lo)
    gemm_tc_nt<<<dim3(DIM/128, 16, 1), blk>>>(pF, Wo, outF, DIM, DHEAD);

    // 7) L2-normalize outF rows
    normalize_rows<<<BATCH*KTOK, 128>>>(outF);

    // 8) A normalization (row-sum reduce folded in)
    scaleA2<<<BATCH*KTOK, 256>>>(outA, pRows);
}